// round 16
// baseline (speedup 1.0000x reference)
#include <cuda_runtime.h>
#include <cuda_bf16.h>
#include <math.h>
#include <string.h>

#define N_NODES 100000
#define N_EDGES 1600000
#define NFEAT   256
#define NHID    64
#define NHEADS  8
#define NH_TOT  (NHEADS*NHID)   // 512
#define NCLASS  97
#define H2STR   100             // padded row stride for g_h2 (16B-aligned rows)
#define ALPHA   0.2f
#define EPSG    1e-16f

typedef unsigned long long ull;
typedef unsigned int u32;

// ---------------- side stream for CSR-build overlap ----------------
struct SideStream {
    cudaStream_t s;
    cudaEvent_t fork, join;
    SideStream() {
        cudaStreamCreateWithFlags(&s, cudaStreamNonBlocking);
        cudaEventCreateWithFlags(&fork, cudaEventDisableTiming);
        cudaEventCreateWithFlags(&join, cudaEventDisableTiming);
    }
};
static SideStream g_ss;

// ---------------- device scratch (no allocs allowed) ----------------
__device__ __align__(16) u32 g_hbw[(size_t)N_NODES * 256];   // layer1 hidden, bf16x2
__device__ __align__(16) u32 g_xhi[(size_t)N_NODES * 256];   // layer1 out, bf16x2 hi
__device__ __align__(16) u32 g_xlo[(size_t)N_NODES * 256];   // layer1 out, bf16x2 lo
__device__ __align__(16) float g_h2[(size_t)N_NODES * H2STR]; // layer2 hidden (padded)
__device__ float g_ssrc [(size_t)N_NODES * NHEADS];
__device__ float g_sdstT[(size_t)NHEADS * N_NODES];   // transposed: [head][node]
__device__ float g_s2src[N_NODES];
__device__ float g_s2dst[N_NODES];
__device__ int   g_counts[N_NODES];
__device__ int   g_fill  [N_NODES];
__device__ int   g_rowptr[N_NODES + 1];
__device__ int   g_csr   [N_EDGES];
__device__ int   g_partials[256];
__device__ int   g_is64;
// pre-split weights (small, L2-resident)
__device__ __nv_bfloat16 g_w1hi[(size_t)NHEADS * NFEAT * NHID];
__device__ __nv_bfloat16 g_w1lo[(size_t)NHEADS * NFEAT * NHID];
__device__ __nv_bfloat16 g_w2hi[(size_t)NH_TOT * 128];
__device__ __nv_bfloat16 g_w2lo[(size_t)NH_TOT * 128];

// ---------------- helpers ----------------
__device__ __forceinline__ void mma16816(float* d, const u32* a, const u32* b) {
    asm volatile(
        "mma.sync.aligned.m16n8k16.row.col.f32.bf16.bf16.f32 "
        "{%0,%1,%2,%3}, {%4,%5,%6,%7}, {%8,%9}, {%0,%1,%2,%3};"
        : "+f"(d[0]), "+f"(d[1]), "+f"(d[2]), "+f"(d[3])
        : "r"(a[0]), "r"(a[1]), "r"(a[2]), "r"(a[3]), "r"(b[0]), "r"(b[1]));
}
__device__ __forceinline__ u32 bf2u(float x, float y) {
    __nv_bfloat162 h = __floats2bfloat162_rn(x, y);   // .x = low
    u32 r; memcpy(&r, &h, 4); return r;
}

// ---------------- edge index readers ----------------
__device__ __forceinline__ int edge_src(const void* ei, int e) {
    if (g_is64) return (int)((const long long*)ei)[e];
    return ((const int*)ei)[e];
}
__device__ __forceinline__ int edge_dst(const void* ei, int e) {
    if (g_is64) return (int)((const long long*)ei)[(size_t)N_EDGES + e];
    return ((const int*)ei)[(size_t)N_EDGES + e];
}

// ---------------- init / detect / weight prep ----------------
__global__ void init_kernel(const int* __restrict__ w) {
    int i = blockIdx.x * blockDim.x + threadIdx.x;
    if (i < N_NODES) { g_counts[i] = 0; g_fill[i] = 0; }
    if (i == 0) g_is64 = 1;
}

__global__ void detect_kernel(const int* __restrict__ w) {
    int i = blockIdx.x * blockDim.x + threadIdx.x;
    if (i < 4096) {
        if (w[2 * i + 1] != 0) g_is64 = 0;  // odd word nonzero => int32 data
    }
}

__global__ void wconv1_kernel(const float* __restrict__ W) {
    int idx = blockIdx.x * blockDim.x + threadIdx.x;
    if (idx >= NHEADS * NFEAT * NHID) return;
    float w = W[idx];
    __nv_bfloat16 hi = __float2bfloat16(w);
    g_w1hi[idx] = hi;
    g_w1lo[idx] = __float2bfloat16(w - __bfloat162float(hi));
}

__global__ void wconv2_kernel(const float* __restrict__ Wo) {
    int idx = blockIdx.x * blockDim.x + threadIdx.x;   // over 512*128
    if (idx >= NH_TOT * 128) return;
    int k = idx >> 7, n = idx & 127;
    float w = (n < NCLASS) ? Wo[(size_t)k * NCLASS + n] : 0.f;
    __nv_bfloat16 hi = __float2bfloat16(w);
    g_w2hi[idx] = hi;
    g_w2lo[idx] = __float2bfloat16(w - __bfloat162float(hi));
}

// ---------------- GEMM1 via mma.sync bf16 split + fused s1 ----------------
// grid (8 heads, ceil(N/128)); head fastest (A-chunk L2 reuse). block 256.
#define OFF_AHI 0        // [128][72] bf16 = 18432
#define OFF_ALO 18432
#define OFF_BHI 36864    // [64][72] bf16 = 9216
#define OFF_BLO 46080
#define OFF_PS  55296    // float[256]
#define G1_SMEM 56320
#define ASTR 72
#define BSTR 72

__global__ void __launch_bounds__(256)
gemm1_mma_kernel(const float* __restrict__ A, const float* __restrict__ a)
{
    extern __shared__ __align__(16) unsigned char smem[];
    __nv_bfloat16* As_hi = (__nv_bfloat16*)(smem + OFF_AHI);
    __nv_bfloat16* As_lo = (__nv_bfloat16*)(smem + OFF_ALO);
    __nv_bfloat16* Bt_hi = (__nv_bfloat16*)(smem + OFF_BHI);
    __nv_bfloat16* Bt_lo = (__nv_bfloat16*)(smem + OFF_BLO);
    float* ps = (float*)(smem + OFF_PS);

    const int head = blockIdx.x;               // fastest-varying
    const int row0 = blockIdx.y * 128;
    const int tid = threadIdx.x;
    const int warp = tid >> 5, lane = tid & 31;
    const int gid = lane >> 2, tig = lane & 3;
    const int mr = (warp >> 1) * 32;
    const int nc = (warp & 1) * 32;
    const size_t wbase = (size_t)head * NFEAT * NHID;

    float d[2][4][4];
#pragma unroll
    for (int mt = 0; mt < 2; mt++)
#pragma unroll
        for (int nt = 0; nt < 4; nt++)
#pragma unroll
            for (int i = 0; i < 4; i++) d[mt][nt][i] = 0.f;

    if (tid < 128) { ps[tid] = 0.f; ps[128 + tid] = 0.f; }

    for (int c = 0; c < 4; c++) {
        // A chunk 128x64: float4 loads, split to bf16 hi/lo
#pragma unroll
        for (int l = 0; l < 8; l++) {
            int i = tid + l * 256;          // 0..2047 float4 units
            int r = i >> 4, q = i & 15;
            int gr = row0 + r;
            float4 f = make_float4(0.f, 0.f, 0.f, 0.f);
            if (gr < N_NODES) f = *(const float4*)&A[(size_t)gr * NFEAT + c * 64 + q * 4];
            __nv_bfloat16 h0 = __float2bfloat16(f.x), h1 = __float2bfloat16(f.y);
            __nv_bfloat16 h2 = __float2bfloat16(f.z), h3 = __float2bfloat16(f.w);
            uint2 hv, lv;
            hv.x = bf2u(f.x, f.y); hv.y = bf2u(f.z, f.w);
            lv.x = bf2u(f.x - __bfloat162float(h0), f.y - __bfloat162float(h1));
            lv.y = bf2u(f.z - __bfloat162float(h2), f.w - __bfloat162float(h3));
            *(uint2*)&As_hi[r * ASTR + q * 4] = hv;
            *(uint2*)&As_lo[r * ASTR + q * 4] = lv;
        }
        // B chunk: pre-split copies
#pragma unroll
        for (int l = 0; l < 16; l++) {
            int i = tid + l * 256;
            int kk = i >> 6, n = i & 63;
            size_t gi = wbase + (size_t)(c * 64 + kk) * NHID + n;
            Bt_hi[n * BSTR + kk] = g_w1hi[gi];
            Bt_lo[n * BSTR + kk] = g_w1lo[gi];
        }
        __syncthreads();

#pragma unroll
        for (int s = 0; s < 4; s++) {
            u32 ahi[2][4], alo[2][4], bhi[4][2], blo[4][2];
            int kb = s * 16 + tig * 2;
#pragma unroll
            for (int mt = 0; mt < 2; mt++) {
                int r0 = mr + mt * 16 + gid;
                ahi[mt][0] = *(const u32*)&As_hi[r0 * ASTR + kb];
                ahi[mt][1] = *(const u32*)&As_hi[(r0 + 8) * ASTR + kb];
                ahi[mt][2] = *(const u32*)&As_hi[r0 * ASTR + kb + 8];
                ahi[mt][3] = *(const u32*)&As_hi[(r0 + 8) * ASTR + kb + 8];
                alo[mt][0] = *(const u32*)&As_lo[r0 * ASTR + kb];
                alo[mt][1] = *(const u32*)&As_lo[(r0 + 8) * ASTR + kb];
                alo[mt][2] = *(const u32*)&As_lo[r0 * ASTR + kb + 8];
                alo[mt][3] = *(const u32*)&As_lo[(r0 + 8) * ASTR + kb + 8];
            }
#pragma unroll
            for (int nt = 0; nt < 4; nt++) {
                int n0 = nc + nt * 8 + gid;
                bhi[nt][0] = *(const u32*)&Bt_hi[n0 * BSTR + kb];
                bhi[nt][1] = *(const u32*)&Bt_hi[n0 * BSTR + kb + 8];
                blo[nt][0] = *(const u32*)&Bt_lo[n0 * BSTR + kb];
                blo[nt][1] = *(const u32*)&Bt_lo[n0 * BSTR + kb + 8];
            }
#pragma unroll
            for (int mt = 0; mt < 2; mt++)
#pragma unroll
                for (int nt = 0; nt < 4; nt++) {
                    mma16816(d[mt][nt], ahi[mt], bhi[nt]);
                    mma16816(d[mt][nt], alo[mt], bhi[nt]);
                    mma16816(d[mt][nt], ahi[mt], blo[nt]);
                }
        }
        __syncthreads();
    }

    // ---- epilogue: store h (bf16x2 packed), fused s1 dots ----
    const float* ak = a + (size_t)head * 2 * NHID;
    float a1v[4][2], a2v[4][2];
#pragma unroll
    for (int nt = 0; nt < 4; nt++) {
        int cn = nc + nt * 8 + tig * 2;
        a1v[nt][0] = ak[cn];      a1v[nt][1] = ak[cn + 1];
        a2v[nt][0] = ak[64 + cn]; a2v[nt][1] = ak[64 + cn + 1];
    }
    float psa[2][2] = {{0.f,0.f},{0.f,0.f}}, psb[2][2] = {{0.f,0.f},{0.f,0.f}};
#pragma unroll
    for (int mt = 0; mt < 2; mt++) {
        int rA = mr + mt * 16 + gid;
        int rB = rA + 8;
        bool okA = (row0 + rA < N_NODES), okB = (row0 + rB < N_NODES);
#pragma unroll
        for (int nt = 0; nt < 4; nt++) {
            int cn = nc + nt * 8 + tig * 2;
            float v0 = d[mt][nt][0], v1 = d[mt][nt][1];
            float v2 = d[mt][nt][2], v3 = d[mt][nt][3];
            if (okA) g_hbw[(size_t)(row0 + rA) * 256 + head * 32 + (cn >> 1)] = bf2u(v0, v1);
            if (okB) g_hbw[(size_t)(row0 + rB) * 256 + head * 32 + (cn >> 1)] = bf2u(v2, v3);
            psa[mt][0] += v0 * a1v[nt][0] + v1 * a1v[nt][1];
            psa[mt][1] += v2 * a1v[nt][0] + v3 * a1v[nt][1];
            psb[mt][0] += v0 * a2v[nt][0] + v1 * a2v[nt][1];
            psb[mt][1] += v2 * a2v[nt][0] + v3 * a2v[nt][1];
        }
    }
#pragma unroll
    for (int mt = 0; mt < 2; mt++)
#pragma unroll
        for (int half = 0; half < 2; half++) {
#pragma unroll
            for (int o = 1; o < 4; o <<= 1) {
                psa[mt][half] += __shfl_xor_sync(0xffffffffu, psa[mt][half], o);
                psb[mt][half] += __shfl_xor_sync(0xffffffffu, psb[mt][half], o);
            }
        }
    if (tig == 0) {
#pragma unroll
        for (int mt = 0; mt < 2; mt++) {
            int rA = mr + mt * 16 + gid, rB = rA + 8;
            atomicAdd(&ps[rA], psa[mt][0]);
            atomicAdd(&ps[rB], psa[mt][1]);
            atomicAdd(&ps[128 + rA], psb[mt][0]);
            atomicAdd(&ps[128 + rB], psb[mt][1]);
        }
    }
    __syncthreads();
    if (tid < 128 && row0 + tid < N_NODES) {
        g_ssrc[(size_t)(row0 + tid) * NHEADS + head] = ps[tid];
        g_sdstT[(size_t)head * N_NODES + row0 + tid] = ps[128 + tid];
    }
}

// ---------------- CSR build ----------------
__global__ void hist_kernel(const void* __restrict__ ei) {
    int e = blockIdx.x * blockDim.x + threadIdx.x;
    if (e >= N_EDGES) return;
    atomicAdd(&g_counts[edge_src(ei, e)], 1);
}

__global__ void chunk_sums_kernel() {
    __shared__ int sh[512];
    int i = blockIdx.x * 512 + threadIdx.x;
    sh[threadIdx.x] = (i < N_NODES) ? g_counts[i] : 0;
    __syncthreads();
#pragma unroll
    for (int s = 256; s > 0; s >>= 1) {
        if (threadIdx.x < s) sh[threadIdx.x] += sh[threadIdx.x + s];
        __syncthreads();
    }
    if (threadIdx.x == 0) g_partials[blockIdx.x] = sh[0];
}

__global__ void scan_partials_kernel(int n) {
    __shared__ int sh[256];
    int v = (threadIdx.x < n) ? g_partials[threadIdx.x] : 0;
    sh[threadIdx.x] = v;
    __syncthreads();
#pragma unroll
    for (int d = 1; d < 256; d <<= 1) {
        int t = (threadIdx.x >= d) ? sh[threadIdx.x - d] : 0;
        __syncthreads();
        sh[threadIdx.x] += t;
        __syncthreads();
    }
    if (threadIdx.x < n) g_partials[threadIdx.x] = sh[threadIdx.x] - v;
}

__global__ void scan_chunks_kernel() {
    __shared__ int sh[512];
    int i = blockIdx.x * 512 + threadIdx.x;
    int v = (i < N_NODES) ? g_counts[i] : 0;
    sh[threadIdx.x] = v;
    __syncthreads();
#pragma unroll
    for (int d = 1; d < 512; d <<= 1) {
        int t = (threadIdx.x >= d) ? sh[threadIdx.x - d] : 0;
        __syncthreads();
        sh[threadIdx.x] += t;
        __syncthreads();
    }
    int incl = sh[threadIdx.x];
    if (i < N_NODES) g_rowptr[i] = g_partials[blockIdx.x] + incl - v;
    if (i == N_NODES - 1) g_rowptr[N_NODES] = g_partials[blockIdx.x] + incl;
}

__global__ void scatter_kernel(const void* __restrict__ ei) {
    int e = blockIdx.x * blockDim.x + threadIdx.x;
    if (e >= N_EDGES) return;
    int s = edge_src(ei, e);
    int d = edge_dst(ei, e);
    int pos = g_rowptr[s] + atomicAdd(&g_fill[s], 1);
    g_csr[pos] = d;
}

// ---------------- agg1: bf16 gather, 4 edges / warp-iter; writes x pre-split --
__global__ __launch_bounds__(256) void agg1_kernel() {
    int lane = threadIdx.x & 31;
    int n = blockIdx.x * 8 + (threadIdx.x >> 5);
    if (n >= N_NODES) return;
    int k = blockIdx.y;
    int beg = g_rowptr[n], end = g_rowptr[n + 1];
    float ssrc = g_ssrc[(size_t)n * NHEADS + k];
    const float* sdT = g_sdstT + (size_t)k * N_NODES;
    const int q8 = lane & 7;
    const int quarter = lane >> 3;
    float acc[8];
#pragma unroll
    for (int i = 0; i < 8; i++) acc[i] = 0.f;
    float rs = 0.f;

    for (int c0 = beg; c0 < end; c0 += 32) {
        int m = end - c0; if (m > 32) m = 32;
        int dst = 0; float e = 0.f;
        if (lane < m) {
            dst = g_csr[c0 + lane];
            float z = ssrc + sdT[dst];
            float lr = fmaxf(z, ALPHA * z);
            e = __expf(-lr);
        }
        for (int j = 0; j < m; j += 4) {
            int jj = j + quarter;
            float ej = __shfl_sync(0xffffffffu, e, jj);
            int   dj = __shfl_sync(0xffffffffu, dst, jj);
            uint4 hv = ((const uint4*)(g_hbw + (size_t)dj * 256 + k * 32))[q8];
            acc[0] += ej * __uint_as_float(hv.x << 16);
            acc[1] += ej * __uint_as_float(hv.x & 0xffff0000u);
            acc[2] += ej * __uint_as_float(hv.y << 16);
            acc[3] += ej * __uint_as_float(hv.y & 0xffff0000u);
            acc[4] += ej * __uint_as_float(hv.z << 16);
            acc[5] += ej * __uint_as_float(hv.z & 0xffff0000u);
            acc[6] += ej * __uint_as_float(hv.w << 16);
            acc[7] += ej * __uint_as_float(hv.w & 0xffff0000u);
            rs += ej;
        }
    }
#pragma unroll
    for (int o = 8; o <= 16; o <<= 1) {
#pragma unroll
        for (int i = 0; i < 8; i++)
            acc[i] += __shfl_xor_sync(0xffffffffu, acc[i], o);
        rs += __shfl_xor_sync(0xffffffffu, rs, o);
    }
    if (lane < 8) {
        float inv = 1.f / (rs + EPSG);
        float v[8];
        __nv_bfloat16 hb[8];
#pragma unroll
        for (int i = 0; i < 8; i++) {
            float t = acc[i] * inv;
            v[i] = (t > 0.f) ? t : expm1f(t);
            hb[i] = __float2bfloat16(v[i]);
        }
        uint4 hv, lv;
        hv.x = bf2u(v[0], v[1]); hv.y = bf2u(v[2], v[3]);
        hv.z = bf2u(v[4], v[5]); hv.w = bf2u(v[6], v[7]);
        lv.x = bf2u(v[0] - __bfloat162float(hb[0]), v[1] - __bfloat162float(hb[1]));
        lv.y = bf2u(v[2] - __bfloat162float(hb[2]), v[3] - __bfloat162float(hb[3]));
        lv.z = bf2u(v[4] - __bfloat162float(hb[4]), v[5] - __bfloat162float(hb[5]));
        lv.w = bf2u(v[6] - __bfloat162float(hb[6]), v[7] - __bfloat162float(hb[7]));
        size_t base = (size_t)n * 256 + k * 32 + lane * 4;
        *(uint4*)&g_xhi[base] = hv;
        *(uint4*)&g_xlo[base] = lv;
    }
}

// ---------------- GEMM2 via mma.sync bf16 split + fused s2 ----------------
#define G2_AHI 0
#define G2_ALO 18432
#define G2_BHI 36864
#define G2_BLO 55296
#define G2_PS  73728
#define G2_SMEM 74752

__global__ void __launch_bounds__(512)
gemm2_mma_kernel(const float* __restrict__ ao)
{
    extern __shared__ __align__(16) unsigned char smem[];
    __nv_bfloat16* As_hi = (__nv_bfloat16*)(smem + G2_AHI);
    __nv_bfloat16* As_lo = (__nv_bfloat16*)(smem + G2_ALO);
    __nv_bfloat16* Bt_hi = (__nv_bfloat16*)(smem + G2_BHI);
    __nv_bfloat16* Bt_lo = (__nv_bfloat16*)(smem + G2_BLO);
    float* ps = (float*)(smem + G2_PS);

    const int row0 = blockIdx.x * 128;
    const int tid = threadIdx.x;
    const int warp = tid >> 5, lane = tid & 31;
    const int gid = lane >> 2, tig = lane & 3;
    const int mr = (warp >> 2) * 32;
    const int nc = (warp & 3) * 32;

    float d[2][4][4];
#pragma unroll
    for (int mt = 0; mt < 2; mt++)
#pragma unroll
        for (int nt = 0; nt < 4; nt++)
#pragma unroll
            for (int i = 0; i < 4; i++) d[mt][nt][i] = 0.f;

    if (tid < 256) ps[tid] = 0.f;

    for (int c = 0; c < 8; c++) {
        // A: pre-split copies (uint2)
#pragma unroll
        for (int l = 0; l < 4; l++) {
            int i = tid + l * 512;          // 0..2047 uint2 units
            int r = i >> 4, kp2 = i & 15;
            int gr = row0 + r;
            uint2 hv = make_uint2(0u, 0u), lv = make_uint2(0u, 0u);
            if (gr < N_NODES) {
                size_t gi = (size_t)gr * 256 + c * 32 + kp2 * 2;
                hv = *(const uint2*)&g_xhi[gi];
                lv = *(const uint2*)&g_xlo[gi];
            }
            *(uint2*)&As_hi[r * ASTR + kp2 * 4] = hv;
            *(uint2*)&As_lo[r * ASTR + kp2 * 4] = lv;
        }
        // B: pre-split copies
#pragma unroll
        for (int l = 0; l < 16; l++) {
            int i = tid + l * 512;
            int kk = i >> 7, n = i & 127;
            size_t gi = (size_t)(c * 64 + kk) * 128 + n;
            Bt_hi[n * BSTR + kk] = g_w2hi[gi];
            Bt_lo[n * BSTR + kk] = g_w2lo[gi];
        }
        __syncthreads();

#pragma unroll
        for (int s = 0; s < 4; s++) {
            u32 ahi[2][4], alo[2][4], bhi[4][2], blo[4][2];
            int kb = s * 16 + tig * 2;
#pragma unroll
            for (int mt = 0; mt < 2; mt++) {
                int r0 = mr + mt * 16 + gid;
                ahi[mt][0] = *(const u32*)&As_hi[r0 * ASTR + kb];
                ahi[mt][1] = *(const u32*)&As_hi[(r0 + 8) * ASTR + kb];
                ahi[mt][2] = *(const u32*)&As_hi[r0 * ASTR + kb + 8];
                ahi[mt][3] = *(const u32*)&As_hi[(r0 + 8) * ASTR + kb + 8];
                alo[mt][0] = *(const u32*)&As_lo[r0 * ASTR + kb];
                alo[mt][1] = *(const u32*)&As_lo[(r0 + 8) * ASTR + kb];
                alo[mt][2] = *(const u32*)&As_lo[r0 * ASTR + kb + 8];
                alo[mt][3] = *(const u32*)&As_lo[(r0 + 8) * ASTR + kb + 8];
            }
#pragma unroll
            for (int nt = 0; nt < 4; nt++) {
                int n0 = nc + nt * 8 + gid;
                bhi[nt][0] = *(const u32*)&Bt_hi[n0 * BSTR + kb];
                bhi[nt][1] = *(const u32*)&Bt_hi[n0 * BSTR + kb + 8];
                blo[nt][0] = *(const u32*)&Bt_lo[n0 * BSTR + kb];
                blo[nt][1] = *(const u32*)&Bt_lo[n0 * BSTR + kb + 8];
            }
#pragma unroll
            for (int mt = 0; mt < 2; mt++)
#pragma unroll
                for (int nt = 0; nt < 4; nt++) {
                    mma16816(d[mt][nt], ahi[mt], bhi[nt]);
                    mma16816(d[mt][nt], alo[mt], bhi[nt]);
                    mma16816(d[mt][nt], ahi[mt], blo[nt]);
                }
        }
        __syncthreads();
    }

    float a1v[4][2], a2v[4][2];
#pragma unroll
    for (int nt = 0; nt < 4; nt++) {
        int cn = nc + nt * 8 + tig * 2;
        a1v[nt][0] = (cn < NCLASS) ? ao[cn] : 0.f;
        a1v[nt][1] = (cn + 1 < NCLASS) ? ao[cn + 1] : 0.f;
        a2v[nt][0] = (cn < NCLASS) ? ao[NCLASS + cn] : 0.f;
        a2v[nt][1] = (cn + 1 < NCLASS) ? ao[NCLASS + cn + 1] : 0.f;
    }
    float psa[2][2] = {{0.f,0.f},{0.f,0.f}}, psb[2][2] = {{0.f,0.f},{0.f,0.f}};
#pragma unroll
    for (int mt = 0; mt < 2; mt++) {
        int rA = mr + mt * 16 + gid;
        int rB = rA + 8;
        bool okA = (row0 + rA < N_NODES), okB = (row0 + rB < N_NODES);
#pragma unroll
        for (int nt = 0; nt < 4; nt++) {
            int cn = nc + nt * 8 + tig * 2;
            float v0 = d[mt][nt][0], v1 = d[mt][nt][1];
            float v2 = d[mt][nt][2], v3 = d[mt][nt][3];
            if (okA && cn < H2STR)     g_h2[(size_t)(row0 + rA) * H2STR + cn]     = v0;
            if (okA && cn + 1 < H2STR) g_h2[(size_t)(row0 + rA) * H2STR + cn + 1] = v1;
            if (okB && cn < H2STR)     g_h2[(size_t)(row0 + rB) * H2STR + cn]     = v2;
            if (okB && cn + 1 < H2STR) g_h2[(size_t)(row0 + rB) * H2STR + cn + 1] = v3;
            psa[mt][0] += v0 * a1v[nt][0] + v1 * a1v[nt][1];
            psa[mt][1] += v2 * a1v[nt][0] + v3 * a1v[nt][1];
            psb[mt][0] += v0 * a2v[nt][0] + v1 * a2v[nt][1];
            psb[mt][1] += v2 * a2v[nt][0] + v3 * a2v[nt][1];
        }
    }
#pragma unroll
    for (int mt = 0; mt < 2; mt++)
#pragma unroll
        for (int half = 0; half < 2; half++) {
#pragma unroll
            for (int o = 1; o < 4; o <<= 1) {
                psa[mt][half] += __shfl_xor_sync(0xffffffffu, psa[mt][half], o);
                psb[mt][half] += __shfl_xor_sync(0xffffffffu, psb[mt][half], o);
            }
        }
    if (tig == 0) {
#pragma unroll
        for (int mt = 0; mt < 2; mt++) {
            int rA = mr + mt * 16 + gid, rB = rA + 8;
            atomicAdd(&ps[rA], psa[mt][0]);
            atomicAdd(&ps[rB], psa[mt][1]);
            atomicAdd(&ps[128 + rA], psb[mt][0]);
            atomicAdd(&ps[128 + rB], psb[mt][1]);
        }
    }
    __syncthreads();
    if (tid < 128 && row0 + tid < N_NODES) {
        g_s2src[row0 + tid] = ps[tid];
        g_s2dst[row0 + tid] = ps[128 + tid];
    }
}

// ---------------- agg2: float4 gather + elu + log_softmax ----------------
__global__ __launch_bounds__(256) void agg2_kernel(float* __restrict__ out) {
    int lane = threadIdx.x & 31;
    int n = blockIdx.x * 8 + (threadIdx.x >> 5);
    if (n >= N_NODES) return;
    int beg = g_rowptr[n], end = g_rowptr[n + 1];
    float ssrc = g_s2src[n];
    const bool ldok = (lane < 25);
    float acc[4] = {0.f, 0.f, 0.f, 0.f};
    float rs = 0.f;

    for (int c0 = beg; c0 < end; c0 += 32) {
        int m = end - c0; if (m > 32) m = 32;
        int dst = 0; float e = 0.f;
        if (lane < m) {
            dst = g_csr[c0 + lane];
            float z = ssrc + g_s2dst[dst];
            float lr = fmaxf(z, ALPHA * z);
            e = __expf(-lr);
        }
        for (int j = 0; j < m; j++) {
            float ej = __shfl_sync(0xffffffffu, e, j);
            int   dj = __shfl_sync(0xffffffffu, dst, j);
            if (ldok) {
                float4 hv = *(const float4*)&g_h2[(size_t)dj * H2STR + lane * 4];
                acc[0] += ej * hv.x;
                acc[1] += ej * hv.y;
                acc[2] += ej * hv.z;
                acc[3] += ej * hv.w;
            }
            rs += ej;
        }
    }
    float inv = 1.f / (rs + EPSG);
    float v[4];
    float mx = -INFINITY;
#pragma unroll
    for (int q = 0; q < 4; q++) {
        int cc = lane * 4 + q;
        if (ldok && cc < NCLASS) {
            float t = acc[q] * inv;
            t = (t > 0.f) ? t : expm1f(t);
            v[q] = t;
            mx = fmaxf(mx, t);
        } else v[q] = -INFINITY;
    }
#pragma unroll
    for (int o = 16; o; o >>= 1) mx = fmaxf(mx, __shfl_xor_sync(0xffffffffu, mx, o));
    float se = 0.f;
#pragma unroll
    for (int q = 0; q < 4; q++) {
        int cc = lane * 4 + q;
        if (ldok && cc < NCLASS) se += __expf(v[q] - mx);
    }
#pragma unroll
    for (int o = 16; o; o >>= 1) se += __shfl_xor_sync(0xffffffffu, se, o);
    float lse = mx + logf(se);
#pragma unroll
    for (int q = 0; q < 4; q++) {
        int cc = lane * 4 + q;
        if (ldok && cc < NCLASS) out[(size_t)n * NCLASS + cc] = v[q] - lse;
    }
}

// ---------------- launch ----------------
extern "C" void kernel_launch(void* const* d_in, const int* in_sizes, int n_in,
                              void* d_out, int out_size) {
    const float* features = (const float*)d_in[0];
    const float* W        = (const float*)d_in[1];
    const float* a        = (const float*)d_in[2];
    const float* W_out    = (const float*)d_in[3];
    const float* a_out    = (const float*)d_in[4];
    const void*  ei       = d_in[5];
    float* out            = (float*)d_out;

    cudaFuncSetAttribute(gemm1_mma_kernel,
                         cudaFuncAttributeMaxDynamicSharedMemorySize, G1_SMEM);
    cudaFuncSetAttribute(gemm2_mma_kernel,
                         cudaFuncAttributeMaxDynamicSharedMemorySize, G2_SMEM);

    // fork: CSR build on side stream, weight prep + gemm1 on main stream
    cudaEventRecord(g_ss.fork, 0);
    cudaStreamWaitEvent(g_ss.s, g_ss.fork, 0);

    init_kernel<<<(N_NODES + 255) / 256, 256, 0, g_ss.s>>>((const int*)ei);
    detect_kernel<<<16, 256, 0, g_ss.s>>>((const int*)ei);
    hist_kernel<<<(N_EDGES + 255) / 256, 256, 0, g_ss.s>>>(ei);
    int nchunks = (N_NODES + 511) / 512;   // 196
    chunk_sums_kernel<<<nchunks, 512, 0, g_ss.s>>>();
    scan_partials_kernel<<<1, 256, 0, g_ss.s>>>(nchunks);
    scan_chunks_kernel<<<nchunks, 512, 0, g_ss.s>>>();
    scatter_kernel<<<(N_EDGES + 255) / 256, 256, 0, g_ss.s>>>(ei);

    wconv1_kernel<<<(NHEADS * NFEAT * NHID + 255) / 256, 256>>>(W);
    wconv2_kernel<<<(NH_TOT * 128 + 255) / 256, 256>>>(W_out);
    gemm1_mma_kernel<<<dim3(NHEADS, (N_NODES + 127) / 128), 256, G1_SMEM>>>(features, a);

    // join: agg1 needs both gemm1 outputs and the CSR
    cudaEventRecord(g_ss.join, g_ss.s);
    cudaStreamWaitEvent(0, g_ss.join, 0);

    agg1_kernel<<<dim3((N_NODES + 7) / 8, NHEADS), 256>>>();

    gemm2_mma_kernel<<<(N_NODES + 127) / 128, 512, G2_SMEM>>>(a_out);
    agg2_kernel<<<(N_NODES + 7) / 8, 256>>>(out);
}

// round 17
// speedup vs baseline: 1.2017x; 1.2017x over previous
#include <cuda_runtime.h>
#include <cuda_bf16.h>
#include <math.h>
#include <string.h>

#define N_NODES 100000
#define N_EDGES 1600000
#define NFEAT   256
#define NHID    64
#define NHEADS  8
#define NH_TOT  (NHEADS*NHID)   // 512
#define NCLASS  97
#define H2STR   100             // padded row stride for g_h2 (16B-aligned rows)
#define ALPHA   0.2f
#define EPSG    1e-16f

typedef unsigned long long ull;
typedef unsigned int u32;

// ---------------- side stream for CSR-build overlap ----------------
struct SideStream {
    cudaStream_t s;
    cudaEvent_t fork, join;
    SideStream() {
        cudaStreamCreateWithFlags(&s, cudaStreamNonBlocking);
        cudaEventCreateWithFlags(&fork, cudaEventDisableTiming);
        cudaEventCreateWithFlags(&join, cudaEventDisableTiming);
    }
};
static SideStream g_ss;

// ---------------- device scratch (no allocs allowed) ----------------
__device__ __align__(16) u32 g_hbw[(size_t)N_NODES * 256];   // layer1 hidden, bf16x2
__device__ float g_x    [(size_t)N_NODES * NH_TOT];   // layer1 output (post elu)
__device__ __align__(16) float g_h2[(size_t)N_NODES * H2STR]; // layer2 hidden (padded)
__device__ float g_ssrc [(size_t)N_NODES * NHEADS];
__device__ float g_sdstT[(size_t)NHEADS * N_NODES];   // transposed: [head][node]
__device__ float g_s2src[N_NODES];
__device__ float g_s2dst[N_NODES];
__device__ int   g_counts[N_NODES];
__device__ int   g_fill  [N_NODES];
__device__ int   g_rowptr[N_NODES + 1];
__device__ int   g_csr   [N_EDGES];
__device__ int   g_partials[256];
__device__ int   g_is64;

// ---------------- helpers ----------------
__device__ __forceinline__ void mma16816(float* d, const u32* a, const u32* b) {
    asm volatile(
        "mma.sync.aligned.m16n8k16.row.col.f32.bf16.bf16.f32 "
        "{%0,%1,%2,%3}, {%4,%5,%6,%7}, {%8,%9}, {%0,%1,%2,%3};"
        : "+f"(d[0]), "+f"(d[1]), "+f"(d[2]), "+f"(d[3])
        : "r"(a[0]), "r"(a[1]), "r"(a[2]), "r"(a[3]), "r"(b[0]), "r"(b[1]));
}
__device__ __forceinline__ u32 bf2u(float x, float y) {
    __nv_bfloat162 h = __floats2bfloat162_rn(x, y);   // .x = low
    u32 r; memcpy(&r, &h, 4); return r;
}

// ---------------- edge index readers ----------------
__device__ __forceinline__ int edge_src(const void* ei, int e) {
    if (g_is64) return (int)((const long long*)ei)[e];
    return ((const int*)ei)[e];
}
__device__ __forceinline__ int edge_dst(const void* ei, int e) {
    if (g_is64) return (int)((const long long*)ei)[(size_t)N_EDGES + e];
    return ((const int*)ei)[(size_t)N_EDGES + e];
}

// ---------------- init / detect ----------------
__global__ void init_kernel(const int* __restrict__ w) {
    int i = blockIdx.x * blockDim.x + threadIdx.x;
    if (i < N_NODES) { g_counts[i] = 0; g_fill[i] = 0; }
    if (i == 0) g_is64 = 1;
}

__global__ void detect_kernel(const int* __restrict__ w) {
    int i = blockIdx.x * blockDim.x + threadIdx.x;
    if (i < 4096) {
        if (w[2 * i + 1] != 0) g_is64 = 0;  // odd word nonzero => int32 data
    }
}

// ---------------- GEMM1 via mma.sync bf16 split + fused s1 ----------------
// grid (8 heads, ceil(N/128)); head fastest (A-chunk L2 reuse). block 256.
#define OFF_AHI 0        // [128][72] bf16 = 18432
#define OFF_ALO 18432
#define OFF_BHI 36864    // [64][72] bf16 = 9216
#define OFF_BLO 46080
#define OFF_PS  55296    // float[256]
#define G1_SMEM 56320
#define ASTR 72
#define BSTR 72

__global__ void __launch_bounds__(256)
gemm1_mma_kernel(const float* __restrict__ A, const float* __restrict__ W,
                 const float* __restrict__ a)
{
    extern __shared__ __align__(16) unsigned char smem[];
    __nv_bfloat16* As_hi = (__nv_bfloat16*)(smem + OFF_AHI);
    __nv_bfloat16* As_lo = (__nv_bfloat16*)(smem + OFF_ALO);
    __nv_bfloat16* Bt_hi = (__nv_bfloat16*)(smem + OFF_BHI);
    __nv_bfloat16* Bt_lo = (__nv_bfloat16*)(smem + OFF_BLO);
    float* ps = (float*)(smem + OFF_PS);

    const int head = blockIdx.x;               // fastest-varying
    const int row0 = blockIdx.y * 128;
    const int tid = threadIdx.x;
    const int warp = tid >> 5, lane = tid & 31;
    const int gid = lane >> 2, tig = lane & 3;
    const int mr = (warp >> 1) * 32;
    const int nc = (warp & 1) * 32;
    const float* Bg = W + (size_t)head * NFEAT * NHID;

    float d[2][4][4];
#pragma unroll
    for (int mt = 0; mt < 2; mt++)
#pragma unroll
        for (int nt = 0; nt < 4; nt++)
#pragma unroll
            for (int i = 0; i < 4; i++) d[mt][nt][i] = 0.f;

    if (tid < 128) { ps[tid] = 0.f; ps[128 + tid] = 0.f; }

    for (int c = 0; c < 4; c++) {
        // A chunk 128x64: float4 loads, split to bf16 hi/lo
#pragma unroll
        for (int l = 0; l < 8; l++) {
            int i = tid + l * 256;          // 0..2047 float4 units
            int r = i >> 4, q = i & 15;
            int gr = row0 + r;
            float4 f = make_float4(0.f, 0.f, 0.f, 0.f);
            if (gr < N_NODES) f = *(const float4*)&A[(size_t)gr * NFEAT + c * 64 + q * 4];
            __nv_bfloat16 h0 = __float2bfloat16(f.x), h1 = __float2bfloat16(f.y);
            __nv_bfloat16 h2 = __float2bfloat16(f.z), h3 = __float2bfloat16(f.w);
            uint2 hv, lv;
            hv.x = bf2u(f.x, f.y); hv.y = bf2u(f.z, f.w);
            lv.x = bf2u(f.x - __bfloat162float(h0), f.y - __bfloat162float(h1));
            lv.y = bf2u(f.z - __bfloat162float(h2), f.w - __bfloat162float(h3));
            *(uint2*)&As_hi[r * ASTR + q * 4] = hv;
            *(uint2*)&As_lo[r * ASTR + q * 4] = lv;
        }
        // B chunk 16x64 per iter: fp32 load + split (W stays L2-hot)
#pragma unroll
        for (int l = 0; l < 16; l++) {
            int i = tid + l * 256;
            int kk = i >> 6, n = i & 63;
            float w = Bg[(size_t)(c * 64 + kk) * NHID + n];
            __nv_bfloat16 hi = __float2bfloat16(w);
            Bt_hi[n * BSTR + kk] = hi;
            Bt_lo[n * BSTR + kk] = __float2bfloat16(w - __bfloat162float(hi));
        }
        __syncthreads();

#pragma unroll
        for (int s = 0; s < 4; s++) {
            u32 ahi[2][4], alo[2][4], bhi[4][2], blo[4][2];
            int kb = s * 16 + tig * 2;
#pragma unroll
            for (int mt = 0; mt < 2; mt++) {
                int r0 = mr + mt * 16 + gid;
                ahi[mt][0] = *(const u32*)&As_hi[r0 * ASTR + kb];
                ahi[mt][1] = *(const u32*)&As_hi[(r0 + 8) * ASTR + kb];
                ahi[mt][2] = *(const u32*)&As_hi[r0 * ASTR + kb + 8];
                ahi[mt][3] = *(const u32*)&As_hi[(r0 + 8) * ASTR + kb + 8];
                alo[mt][0] = *(const u32*)&As_lo[r0 * ASTR + kb];
                alo[mt][1] = *(const u32*)&As_lo[(r0 + 8) * ASTR + kb];
                alo[mt][2] = *(const u32*)&As_lo[r0 * ASTR + kb + 8];
                alo[mt][3] = *(const u32*)&As_lo[(r0 + 8) * ASTR + kb + 8];
            }
#pragma unroll
            for (int nt = 0; nt < 4; nt++) {
                int n0 = nc + nt * 8 + gid;
                bhi[nt][0] = *(const u32*)&Bt_hi[n0 * BSTR + kb];
                bhi[nt][1] = *(const u32*)&Bt_hi[n0 * BSTR + kb + 8];
                blo[nt][0] = *(const u32*)&Bt_lo[n0 * BSTR + kb];
                blo[nt][1] = *(const u32*)&Bt_lo[n0 * BSTR + kb + 8];
            }
#pragma unroll
            for (int mt = 0; mt < 2; mt++)
#pragma unroll
                for (int nt = 0; nt < 4; nt++) {
                    mma16816(d[mt][nt], ahi[mt], bhi[nt]);
                    mma16816(d[mt][nt], alo[mt], bhi[nt]);
                    mma16816(d[mt][nt], ahi[mt], blo[nt]);
                }
        }
        __syncthreads();
    }

    // ---- epilogue: store h (bf16x2 packed), fused s1 dots ----
    const float* ak = a + (size_t)head * 2 * NHID;
    float a1v[4][2], a2v[4][2];
#pragma unroll
    for (int nt = 0; nt < 4; nt++) {
        int cn = nc + nt * 8 + tig * 2;
        a1v[nt][0] = ak[cn];      a1v[nt][1] = ak[cn + 1];
        a2v[nt][0] = ak[64 + cn]; a2v[nt][1] = ak[64 + cn + 1];
    }
    float psa[2][2] = {{0.f,0.f},{0.f,0.f}}, psb[2][2] = {{0.f,0.f},{0.f,0.f}};
#pragma unroll
    for (int mt = 0; mt < 2; mt++) {
        int rA = mr + mt * 16 + gid;
        int rB = rA + 8;
        bool okA = (row0 + rA < N_NODES), okB = (row0 + rB < N_NODES);
#pragma unroll
        for (int nt = 0; nt < 4; nt++) {
            int cn = nc + nt * 8 + tig * 2;
            float v0 = d[mt][nt][0], v1 = d[mt][nt][1];
            float v2 = d[mt][nt][2], v3 = d[mt][nt][3];
            if (okA) g_hbw[(size_t)(row0 + rA) * 256 + head * 32 + (cn >> 1)] = bf2u(v0, v1);
            if (okB) g_hbw[(size_t)(row0 + rB) * 256 + head * 32 + (cn >> 1)] = bf2u(v2, v3);
            psa[mt][0] += v0 * a1v[nt][0] + v1 * a1v[nt][1];
            psa[mt][1] += v2 * a1v[nt][0] + v3 * a1v[nt][1];
            psb[mt][0] += v0 * a2v[nt][0] + v1 * a2v[nt][1];
            psb[mt][1] += v2 * a2v[nt][0] + v3 * a2v[nt][1];
        }
    }
#pragma unroll
    for (int mt = 0; mt < 2; mt++)
#pragma unroll
        for (int half = 0; half < 2; half++) {
#pragma unroll
            for (int o = 1; o < 4; o <<= 1) {
                psa[mt][half] += __shfl_xor_sync(0xffffffffu, psa[mt][half], o);
                psb[mt][half] += __shfl_xor_sync(0xffffffffu, psb[mt][half], o);
            }
        }
    if (tig == 0) {
#pragma unroll
        for (int mt = 0; mt < 2; mt++) {
            int rA = mr + mt * 16 + gid, rB = rA + 8;
            atomicAdd(&ps[rA], psa[mt][0]);
            atomicAdd(&ps[rB], psa[mt][1]);
            atomicAdd(&ps[128 + rA], psb[mt][0]);
            atomicAdd(&ps[128 + rB], psb[mt][1]);
        }
    }
    __syncthreads();
    if (tid < 128 && row0 + tid < N_NODES) {
        g_ssrc[(size_t)(row0 + tid) * NHEADS + head] = ps[tid];
        g_sdstT[(size_t)head * N_NODES + row0 + tid] = ps[128 + tid];
    }
}

// ---------------- CSR build ----------------
__global__ void hist_kernel(const void* __restrict__ ei) {
    int e = blockIdx.x * blockDim.x + threadIdx.x;
    if (e >= N_EDGES) return;
    atomicAdd(&g_counts[edge_src(ei, e)], 1);
}

__global__ void chunk_sums_kernel() {
    __shared__ int sh[512];
    int i = blockIdx.x * 512 + threadIdx.x;
    sh[threadIdx.x] = (i < N_NODES) ? g_counts[i] : 0;
    __syncthreads();
#pragma unroll
    for (int s = 256; s > 0; s >>= 1) {
        if (threadIdx.x < s) sh[threadIdx.x] += sh[threadIdx.x + s];
        __syncthreads();
    }
    if (threadIdx.x == 0) g_partials[blockIdx.x] = sh[0];
}

__global__ void scan_partials_kernel(int n) {
    __shared__ int sh[256];
    int v = (threadIdx.x < n) ? g_partials[threadIdx.x] : 0;
    sh[threadIdx.x] = v;
    __syncthreads();
#pragma unroll
    for (int d = 1; d < 256; d <<= 1) {
        int t = (threadIdx.x >= d) ? sh[threadIdx.x - d] : 0;
        __syncthreads();
        sh[threadIdx.x] += t;
        __syncthreads();
    }
    if (threadIdx.x < n) g_partials[threadIdx.x] = sh[threadIdx.x] - v;
}

__global__ void scan_chunks_kernel() {
    __shared__ int sh[512];
    int i = blockIdx.x * 512 + threadIdx.x;
    int v = (i < N_NODES) ? g_counts[i] : 0;
    sh[threadIdx.x] = v;
    __syncthreads();
#pragma unroll
    for (int d = 1; d < 512; d <<= 1) {
        int t = (threadIdx.x >= d) ? sh[threadIdx.x - d] : 0;
        __syncthreads();
        sh[threadIdx.x] += t;
        __syncthreads();
    }
    int incl = sh[threadIdx.x];
    if (i < N_NODES) g_rowptr[i] = g_partials[blockIdx.x] + incl - v;
    if (i == N_NODES - 1) g_rowptr[N_NODES] = g_partials[blockIdx.x] + incl;
}

__global__ void scatter_kernel(const void* __restrict__ ei) {
    int e = blockIdx.x * blockDim.x + threadIdx.x;
    if (e >= N_EDGES) return;
    int s = edge_src(ei, e);
    int d = edge_dst(ei, e);
    int pos = g_rowptr[s] + atomicAdd(&g_fill[s], 1);
    g_csr[pos] = d;
}

// ---------------- agg1: bf16 gather, 4 edges / warp-iter via LDG.128 ----
__global__ __launch_bounds__(256) void agg1_kernel() {
    int lane = threadIdx.x & 31;
    int n = blockIdx.x * 8 + (threadIdx.x >> 5);
    if (n >= N_NODES) return;
    int k = blockIdx.y;
    int beg = g_rowptr[n], end = g_rowptr[n + 1];
    float ssrc = g_ssrc[(size_t)n * NHEADS + k];
    const float* sdT = g_sdstT + (size_t)k * N_NODES;
    const int q8 = lane & 7;
    const int quarter = lane >> 3;
    float acc[8];
#pragma unroll
    for (int i = 0; i < 8; i++) acc[i] = 0.f;
    float rs = 0.f;

    for (int c0 = beg; c0 < end; c0 += 32) {
        int m = end - c0; if (m > 32) m = 32;
        int dst = 0; float e = 0.f;
        if (lane < m) {
            dst = g_csr[c0 + lane];
            float z = ssrc + sdT[dst];
            float lr = fmaxf(z, ALPHA * z);
            e = __expf(-lr);
        }
        for (int j = 0; j < m; j += 4) {
            int jj = j + quarter;
            float ej = __shfl_sync(0xffffffffu, e, jj);
            int   dj = __shfl_sync(0xffffffffu, dst, jj);
            uint4 hv = ((const uint4*)(g_hbw + (size_t)dj * 256 + k * 32))[q8];
            acc[0] += ej * __uint_as_float(hv.x << 16);
            acc[1] += ej * __uint_as_float(hv.x & 0xffff0000u);
            acc[2] += ej * __uint_as_float(hv.y << 16);
            acc[3] += ej * __uint_as_float(hv.y & 0xffff0000u);
            acc[4] += ej * __uint_as_float(hv.z << 16);
            acc[5] += ej * __uint_as_float(hv.z & 0xffff0000u);
            acc[6] += ej * __uint_as_float(hv.w << 16);
            acc[7] += ej * __uint_as_float(hv.w & 0xffff0000u);
            rs += ej;
        }
    }
#pragma unroll
    for (int o = 8; o <= 16; o <<= 1) {
#pragma unroll
        for (int i = 0; i < 8; i++)
            acc[i] += __shfl_xor_sync(0xffffffffu, acc[i], o);
        rs += __shfl_xor_sync(0xffffffffu, rs, o);
    }
    if (lane < 8) {
        float inv = 1.f / (rs + EPSG);
        float v[8];
#pragma unroll
        for (int i = 0; i < 8; i++) {
            float t = acc[i] * inv;
            v[i] = (t > 0.f) ? t : expm1f(t);
        }
        float* xo = &g_x[(size_t)n * NH_TOT + k * NHID + lane * 8];
        *(float4*)xo       = make_float4(v[0], v[1], v[2], v[3]);
        *(float4*)(xo + 4) = make_float4(v[4], v[5], v[6], v[7]);
    }
}

// ---------------- GEMM2 via mma.sync bf16 split + fused s2 ----------------
#define G2_AHI 0
#define G2_ALO 18432
#define G2_BHI 36864
#define G2_BLO 55296
#define G2_PS  73728
#define G2_SMEM 74752

__global__ void __launch_bounds__(512)
gemm2_mma_kernel(const float* __restrict__ Wo, const float* __restrict__ ao)
{
    extern __shared__ __align__(16) unsigned char smem[];
    __nv_bfloat16* As_hi = (__nv_bfloat16*)(smem + G2_AHI);
    __nv_bfloat16* As_lo = (__nv_bfloat16*)(smem + G2_ALO);
    __nv_bfloat16* Bt_hi = (__nv_bfloat16*)(smem + G2_BHI);
    __nv_bfloat16* Bt_lo = (__nv_bfloat16*)(smem + G2_BLO);
    float* ps = (float*)(smem + G2_PS);

    const int row0 = blockIdx.x * 128;
    const int tid = threadIdx.x;
    const int warp = tid >> 5, lane = tid & 31;
    const int gid = lane >> 2, tig = lane & 3;
    const int mr = (warp >> 2) * 32;
    const int nc = (warp & 3) * 32;

    float d[2][4][4];
#pragma unroll
    for (int mt = 0; mt < 2; mt++)
#pragma unroll
        for (int nt = 0; nt < 4; nt++)
#pragma unroll
            for (int i = 0; i < 4; i++) d[mt][nt][i] = 0.f;

    if (tid < 256) ps[tid] = 0.f;

    for (int c = 0; c < 8; c++) {
#pragma unroll
        for (int l = 0; l < 8; l++) {
            int i = tid + l * 512;
            int r = i >> 5, kp = i & 31;
            int gr = row0 + r;
            float2 f = make_float2(0.f, 0.f);
            if (gr < N_NODES) f = *(const float2*)&g_x[(size_t)gr * NH_TOT + c * 64 + kp * 2];
            __nv_bfloat16 hx = __float2bfloat16(f.x), hy = __float2bfloat16(f.y);
            float rx = f.x - __bfloat162float(hx), ry = f.y - __bfloat162float(hy);
            __nv_bfloat162 hi2; hi2.x = hx; hi2.y = hy;
            __nv_bfloat162 lo2; lo2.x = __float2bfloat16(rx); lo2.y = __float2bfloat16(ry);
            u32 hv, lv; memcpy(&hv, &hi2, 4); memcpy(&lv, &lo2, 4);
            *(u32*)&As_hi[r * ASTR + kp * 2] = hv;
            *(u32*)&As_lo[r * ASTR + kp * 2] = lv;
        }
#pragma unroll
        for (int l = 0; l < 16; l++) {
            int i = tid + l * 512;
            int kk = i >> 7, n = i & 127;
            float w = (n < NCLASS) ? Wo[(size_t)(c * 64 + kk) * NCLASS + n] : 0.f;
            __nv_bfloat16 hi = __float2bfloat16(w);
            Bt_hi[n * BSTR + kk] = hi;
            Bt_lo[n * BSTR + kk] = __float2bfloat16(w - __bfloat162float(hi));
        }
        __syncthreads();

#pragma unroll
        for (int s = 0; s < 4; s++) {
            u32 ahi[2][4], alo[2][4], bhi[4][2], blo[4][2];
            int kb = s * 16 + tig * 2;
#pragma unroll
            for (int mt = 0; mt < 2; mt++) {
                int r0 = mr + mt * 16 + gid;
                ahi[mt][0] = *(const u32*)&As_hi[r0 * ASTR + kb];
                ahi[mt][1] = *(const u32*)&As_hi[(r0 + 8) * ASTR + kb];
                ahi[mt][2] = *(const u32*)&As_hi[r0 * ASTR + kb + 8];
                ahi[mt][3] = *(const u32*)&As_hi[(r0 + 8) * ASTR + kb + 8];
                alo[mt][0] = *(const u32*)&As_lo[r0 * ASTR + kb];
                alo[mt][1] = *(const u32*)&As_lo[(r0 + 8) * ASTR + kb];
                alo[mt][2] = *(const u32*)&As_lo[r0 * ASTR + kb + 8];
                alo[mt][3] = *(const u32*)&As_lo[(r0 + 8) * ASTR + kb + 8];
            }
#pragma unroll
            for (int nt = 0; nt < 4; nt++) {
                int n0 = nc + nt * 8 + gid;
                bhi[nt][0] = *(const u32*)&Bt_hi[n0 * BSTR + kb];
                bhi[nt][1] = *(const u32*)&Bt_hi[n0 * BSTR + kb + 8];
                blo[nt][0] = *(const u32*)&Bt_lo[n0 * BSTR + kb];
                blo[nt][1] = *(const u32*)&Bt_lo[n0 * BSTR + kb + 8];
            }
#pragma unroll
            for (int mt = 0; mt < 2; mt++)
#pragma unroll
                for (int nt = 0; nt < 4; nt++) {
                    mma16816(d[mt][nt], ahi[mt], bhi[nt]);
                    mma16816(d[mt][nt], alo[mt], bhi[nt]);
                    mma16816(d[mt][nt], ahi[mt], blo[nt]);
                }
        }
        __syncthreads();
    }

    float a1v[4][2], a2v[4][2];
#pragma unroll
    for (int nt = 0; nt < 4; nt++) {
        int cn = nc + nt * 8 + tig * 2;
        a1v[nt][0] = (cn < NCLASS) ? ao[cn] : 0.f;
        a1v[nt][1] = (cn + 1 < NCLASS) ? ao[cn + 1] : 0.f;
        a2v[nt][0] = (cn < NCLASS) ? ao[NCLASS + cn] : 0.f;
        a2v[nt][1] = (cn + 1 < NCLASS) ? ao[NCLASS + cn + 1] : 0.f;
    }
    float psa[2][2] = {{0.f,0.f},{0.f,0.f}}, psb[2][2] = {{0.f,0.f},{0.f,0.f}};
#pragma unroll
    for (int mt = 0; mt < 2; mt++) {
        int rA = mr + mt * 16 + gid;
        int rB = rA + 8;
        bool okA = (row0 + rA < N_NODES), okB = (row0 + rB < N_NODES);
#pragma unroll
        for (int nt = 0; nt < 4; nt++) {
            int cn = nc + nt * 8 + tig * 2;
            float v0 = d[mt][nt][0], v1 = d[mt][nt][1];
            float v2 = d[mt][nt][2], v3 = d[mt][nt][3];
            if (okA && cn < H2STR)     g_h2[(size_t)(row0 + rA) * H2STR + cn]     = v0;
            if (okA && cn + 1 < H2STR) g_h2[(size_t)(row0 + rA) * H2STR + cn + 1] = v1;
            if (okB && cn < H2STR)     g_h2[(size_t)(row0 + rB) * H2STR + cn]     = v2;
            if (okB && cn + 1 < H2STR) g_h2[(size_t)(row0 + rB) * H2STR + cn + 1] = v3;
            psa[mt][0] += v0 * a1v[nt][0] + v1 * a1v[nt][1];
            psa[mt][1] += v2 * a1v[nt][0] + v3 * a1v[nt][1];
            psb[mt][0] += v0 * a2v[nt][0] + v1 * a2v[nt][1];
            psb[mt][1] += v2 * a2v[nt][0] + v3 * a2v[nt][1];
        }
    }
#pragma unroll
    for (int mt = 0; mt < 2; mt++)
#pragma unroll
        for (int half = 0; half < 2; half++) {
#pragma unroll
            for (int o = 1; o < 4; o <<= 1) {
                psa[mt][half] += __shfl_xor_sync(0xffffffffu, psa[mt][half], o);
                psb[mt][half] += __shfl_xor_sync(0xffffffffu, psb[mt][half], o);
            }
        }
    if (tig == 0) {
#pragma unroll
        for (int mt = 0; mt < 2; mt++) {
            int rA = mr + mt * 16 + gid, rB = rA + 8;
            atomicAdd(&ps[rA], psa[mt][0]);
            atomicAdd(&ps[rB], psa[mt][1]);
            atomicAdd(&ps[128 + rA], psb[mt][0]);
            atomicAdd(&ps[128 + rB], psb[mt][1]);
        }
    }
    __syncthreads();
    if (tid < 128 && row0 + tid < N_NODES) {
        g_s2src[row0 + tid] = ps[tid];
        g_s2dst[row0 + tid] = ps[128 + tid];
    }
}

// ---------------- agg2: float4 gather + elu + log_softmax ----------------
__global__ __launch_bounds__(256) void agg2_kernel(float* __restrict__ out) {
    int lane = threadIdx.x & 31;
    int n = blockIdx.x * 8 + (threadIdx.x >> 5);
    if (n >= N_NODES) return;
    int beg = g_rowptr[n], end = g_rowptr[n + 1];
    float ssrc = g_s2src[n];
    const bool ldok = (lane < 25);
    float acc[4] = {0.f, 0.f, 0.f, 0.f};
    float rs = 0.f;

    for (int c0 = beg; c0 < end; c0 += 32) {
        int m = end - c0; if (m > 32) m = 32;
        int dst = 0; float e = 0.f;
        if (lane < m) {
            dst = g_csr[c0 + lane];
            float z = ssrc + g_s2dst[dst];
            float lr = fmaxf(z, ALPHA * z);
            e = __expf(-lr);
        }
        for (int j = 0; j < m; j++) {
            float ej = __shfl_sync(0xffffffffu, e, j);
            int   dj = __shfl_sync(0xffffffffu, dst, j);
            if (ldok) {
                float4 hv = *(const float4*)&g_h2[(size_t)dj * H2STR + lane * 4];
                acc[0] += ej * hv.x;
                acc[1] += ej * hv.y;
                acc[2] += ej * hv.z;
                acc[3] += ej * hv.w;
            }
            rs += ej;
        }
    }
    float inv = 1.f / (rs + EPSG);
    float v[4];
    float mx = -INFINITY;
#pragma unroll
    for (int q = 0; q < 4; q++) {
        int cc = lane * 4 + q;
        if (ldok && cc < NCLASS) {
            float t = acc[q] * inv;
            t = (t > 0.f) ? t : expm1f(t);
            v[q] = t;
            mx = fmaxf(mx, t);
        } else v[q] = -INFINITY;
    }
#pragma unroll
    for (int o = 16; o; o >>= 1) mx = fmaxf(mx, __shfl_xor_sync(0xffffffffu, mx, o));
    float se = 0.f;
#pragma unroll
    for (int q = 0; q < 4; q++) {
        int cc = lane * 4 + q;
        if (ldok && cc < NCLASS) se += __expf(v[q] - mx);
    }
#pragma unroll
    for (int o = 16; o; o >>= 1) se += __shfl_xor_sync(0xffffffffu, se, o);
    float lse = mx + logf(se);
#pragma unroll
    for (int q = 0; q < 4; q++) {
        int cc = lane * 4 + q;
        if (ldok && cc < NCLASS) out[(size_t)n * NCLASS + cc] = v[q] - lse;
    }
}

// ---------------- launch ----------------
extern "C" void kernel_launch(void* const* d_in, const int* in_sizes, int n_in,
                              void* d_out, int out_size) {
    const float* features = (const float*)d_in[0];
    const float* W        = (const float*)d_in[1];
    const float* a        = (const float*)d_in[2];
    const float* W_out    = (const float*)d_in[3];
    const float* a_out    = (const float*)d_in[4];
    const void*  ei       = d_in[5];
    float* out            = (float*)d_out;

    cudaFuncSetAttribute(gemm1_mma_kernel,
                         cudaFuncAttributeMaxDynamicSharedMemorySize, G1_SMEM);
    cudaFuncSetAttribute(gemm2_mma_kernel,
                         cudaFuncAttributeMaxDynamicSharedMemorySize, G2_SMEM);

    // fork: CSR build on side stream, gemm1 on main stream (independent work)
    cudaEventRecord(g_ss.fork, 0);
    cudaStreamWaitEvent(g_ss.s, g_ss.fork, 0);

    init_kernel<<<(N_NODES + 255) / 256, 256, 0, g_ss.s>>>((const int*)ei);
    detect_kernel<<<16, 256, 0, g_ss.s>>>((const int*)ei);
    hist_kernel<<<(N_EDGES + 255) / 256, 256, 0, g_ss.s>>>(ei);
    int nchunks = (N_NODES + 511) / 512;   // 196
    chunk_sums_kernel<<<nchunks, 512, 0, g_ss.s>>>();
    scan_partials_kernel<<<1, 256, 0, g_ss.s>>>(nchunks);
    scan_chunks_kernel<<<nchunks, 512, 0, g_ss.s>>>();
    scatter_kernel<<<(N_EDGES + 255) / 256, 256, 0, g_ss.s>>>(ei);

    gemm1_mma_kernel<<<dim3(NHEADS, (N_NODES + 127) / 128), 256, G1_SMEM>>>(features, W, a);

    // join: agg1 needs both gemm1 outputs and the CSR
    cudaEventRecord(g_ss.join, g_ss.s);
    cudaStreamWaitEvent(0, g_ss.join, 0);

    agg1_kernel<<<dim3((N_NODES + 7) / 8, NHEADS), 256>>>();

    gemm2_mma_kernel<<<(N_NODES + 127) / 128, 512, G2_SMEM>>>(W_out, a_out);
    agg2_kernel<<<(N_NODES + 7) / 8, 256>>>(out);
}